// round 3
// baseline (speedup 1.0000x reference)
#include <cuda_runtime.h>
#include <cuda_bf16.h>
#include <cstdint>
#include <math.h>

// Problem constants
#define BB 64
#define SS 512
#define EE 128
#define HH 1024
#define VV 128
#define OO 128
#define NBLK 128          // GRU blocks; each owns 8 j-columns (x3 gates = 24 cols)
#define HP 136            // padded row length (elements) for h chunks in SMEM
#define WP 1032           // padded row length (elements) for weight cols in SMEM

// ---------------- device scratch (no runtime allocation allowed) ------------
__device__ __nv_bfloat16 g_h_hi[(size_t)(SS + 1) * BB * HH];  // h history, hi part
__device__ __nv_bfloat16 g_h_lo[(size_t)(SS + 1) * BB * HH];  // h history, lo part
__device__ __nv_bfloat16 g_Wg_hi[(size_t)NBLK * 24 * HH];     // packed gate weights hi
__device__ __nv_bfloat16 g_Wg_lo[(size_t)NBLK * 24 * HH];     // packed gate weights lo
__device__ float g_P[(size_t)VV * 3 * HH];                    // input preacts per token
__device__ __nv_bfloat16 g_WcT_hi[(size_t)OO * HH];           // (Wh@Wo)^T hi  [o][k]
__device__ __nv_bfloat16 g_WcT_lo[(size_t)OO * HH];           // (Wh@Wo)^T lo
__device__ float g_bc[OO];                                    // bh@Wo + bo
__device__ unsigned g_bar[SS];                                // per-step barrier counters

// ---------------- tiny helpers ----------------------------------------------
__device__ __forceinline__ void cp16(void* dst, const void* src) {
    unsigned d = (unsigned)__cvta_generic_to_shared(dst);
    asm volatile("cp.async.cg.shared.global [%0], [%1], 16;\n" ::"r"(d), "l"(src));
}
__device__ __forceinline__ void cp_commit() { asm volatile("cp.async.commit_group;\n"); }

__device__ __forceinline__ void ldsm4(uint32_t* r, uint32_t saddr) {
    asm volatile("ldmatrix.sync.aligned.m8n8.x4.shared.b16 {%0,%1,%2,%3}, [%4];\n"
                 : "=r"(r[0]), "=r"(r[1]), "=r"(r[2]), "=r"(r[3]) : "r"(saddr));
}
__device__ __forceinline__ void ldsm2(uint32_t* r, uint32_t saddr) {
    asm volatile("ldmatrix.sync.aligned.m8n8.x2.shared.b16 {%0,%1}, [%2];\n"
                 : "=r"(r[0]), "=r"(r[1]) : "r"(saddr));
}
__device__ __forceinline__ void mma_bf16(float* c, const uint32_t* a, const uint32_t* b) {
    asm volatile(
        "mma.sync.aligned.m16n8k16.row.col.f32.bf16.bf16.f32 "
        "{%0,%1,%2,%3},{%4,%5,%6,%7},{%8,%9},{%0,%1,%2,%3};\n"
        : "+f"(c[0]), "+f"(c[1]), "+f"(c[2]), "+f"(c[3])
        : "r"(a[0]), "r"(a[1]), "r"(a[2]), "r"(a[3]), "r"(b[0]), "r"(b[1]));
}
__device__ __forceinline__ float sigf(float x) { return 1.0f / (1.0f + expf(-x)); }

// ============================================================================
// init kernels
// ============================================================================
__global__ void k_zero_bar() {
    int i = blockIdx.x * blockDim.x + threadIdx.x;
    if (i < SS) g_bar[i] = 0u;
}

__global__ void k_pack_carry(const float* __restrict__ carry) {
    int i = blockIdx.x * blockDim.x + threadIdx.x;
    if (i >= BB * HH) return;
    float v = carry[i];
    __nv_bfloat16 hi = __float2bfloat16_rn(v);
    g_h_hi[i] = hi;
    g_h_lo[i] = __float2bfloat16_rn(v - __bfloat162float(hi));
}

__global__ void k_pack_w(const float* __restrict__ Whr, const float* __restrict__ Whz,
                         const float* __restrict__ Whn) {
    int idx = blockIdx.x * blockDim.x + threadIdx.x;
    if (idx >= NBLK * 24 * HH) return;
    int jb = idx / (24 * HH);
    int rem = idx - jb * (24 * HH);
    int c = rem >> 10;         // 0..23
    int k = rem & (HH - 1);
    int g = c >> 3;
    int j = (jb << 3) + (c & 7);
    const float* Wg = (g == 0) ? Whr : (g == 1) ? Whz : Whn;
    float v = Wg[(size_t)k * HH + j];
    __nv_bfloat16 hi = __float2bfloat16_rn(v);
    g_Wg_hi[idx] = hi;
    g_Wg_lo[idx] = __float2bfloat16_rn(v - __bfloat162float(hi));
}

__global__ void k_build_P(const float* __restrict__ emb,
                          const float* __restrict__ Wir, const float* __restrict__ bir,
                          const float* __restrict__ Wiz, const float* __restrict__ biz,
                          const float* __restrict__ Win, const float* __restrict__ bin_) {
    int idx = blockIdx.x * blockDim.x + threadIdx.x;
    if (idx >= VV * 3 * HH) return;
    int j = idx & (HH - 1);
    int g = (idx >> 10) % 3;
    int v = idx / (3 * HH);
    const float* W = (g == 0) ? Wir : (g == 1) ? Wiz : Win;
    const float* bb = (g == 0) ? bir : (g == 1) ? biz : bin_;
    float a = bb[j];
#pragma unroll 8
    for (int k = 0; k < EE; k++) a += emb[v * EE + k] * W[(size_t)k * HH + j];
    g_P[idx] = a;
}

__global__ void k_build_Wc(const float* __restrict__ Wh, const float* __restrict__ bh,
                           const float* __restrict__ Wo, const float* __restrict__ bo) {
    int idx = blockIdx.x * blockDim.x + threadIdx.x;
    if (idx >= HH * OO) return;
    int o = idx & (OO - 1);
    int k = idx >> 7;
    float a = 0.f;
#pragma unroll 8
    for (int j = 0; j < HH; j++) a += Wh[(size_t)k * HH + j] * Wo[(size_t)j * OO + o];
    __nv_bfloat16 hi = __float2bfloat16_rn(a);
    g_WcT_hi[(size_t)o * HH + k] = hi;
    g_WcT_lo[(size_t)o * HH + k] = __float2bfloat16_rn(a - __bfloat162float(hi));
    if (k == 0) {
        float c = bo[o];
#pragma unroll 8
        for (int j = 0; j < HH; j++) c += bh[j] * Wo[(size_t)j * OO + o];
        g_bc[o] = c;
    }
}

// ============================================================================
// persistent GRU kernel: 128 CTAs x 128 threads, weights SMEM-resident
// ============================================================================
__global__ void __launch_bounds__(128, 1)
k_gru(const int* __restrict__ inputs, const float* __restrict__ bhn) {
    extern __shared__ char smem[];
    __nv_bfloat16* whi = (__nv_bfloat16*)smem;             // 24*WP
    __nv_bfloat16* wlo = whi + 24 * WP;                    // 24*WP
    __nv_bfloat16* hbh = wlo + 24 * WP;                    // 2*64*HP
    __nv_bfloat16* hbl = hbh + 2 * 64 * HP;                // 2*64*HP
    int* stok = (int*)(hbl + 2 * 64 * HP);                 // 64
    float* sbhn = (float*)(stok + 64);                     // 8

    const int tid = threadIdx.x;
    const int jb = blockIdx.x;
    const int w = tid >> 5, lane = tid & 31;

    // --- one-time weight slice load (96KB) ---
    {
        const __nv_bfloat16* srcH = g_Wg_hi + (size_t)jb * 24 * HH;
        const __nv_bfloat16* srcL = g_Wg_lo + (size_t)jb * 24 * HH;
        for (int u = tid; u < 3072; u += 128) {
            int c = u >> 7, q = u & 127;
            cp16(whi + c * WP + q * 8, srcH + c * HH + q * 8);
            cp16(wlo + c * WP + q * 8, srcL + c * HH + q * 8);
        }
    }
    if (tid < 8) sbhn[tid] = bhn[jb * 8 + tid];
    cp_commit();

    const uint32_t s_hbh = (uint32_t)__cvta_generic_to_shared(hbh);
    const uint32_t s_hbl = (uint32_t)__cvta_generic_to_shared(hbl);
    const uint32_t s_whi = (uint32_t)__cvta_generic_to_shared(whi);
    const uint32_t s_wlo = (uint32_t)__cvta_generic_to_shared(wlo);

    const int a_row = (w << 4) + (lane & 15);
    const int a_k   = (lane >> 4) << 3;
    const int b_col = lane & 7;
    const int b_k   = ((lane >> 3) & 1) << 3;

    for (int t = 0; t < SS; t++) {
        if (tid < 64) stok[tid] = inputs[tid * SS + t];
        const __nv_bfloat16* hH = g_h_hi + (size_t)t * (BB * HH);
        const __nv_bfloat16* hL = g_h_lo + (size_t)t * (BB * HH);

        auto prefetch = [&](int kc, int buf) {
            const __nv_bfloat16* sh = hH + kc * 128;
            const __nv_bfloat16* sl = hL + kc * 128;
            __nv_bfloat16* dh = hbh + buf * (64 * HP);
            __nv_bfloat16* dl = hbl + buf * (64 * HP);
            for (int u = tid; u < 1024; u += 128) {
                int row = u >> 4, q = u & 15;
                cp16(dh + row * HP + q * 8, sh + row * HH + q * 8);
                cp16(dl + row * HP + q * 8, sl + row * HH + q * 8);
            }
            cp_commit();
        };

        float accR[4] = {0.f, 0.f, 0.f, 0.f};
        float accZ[4] = {0.f, 0.f, 0.f, 0.f};
        float accN[4] = {0.f, 0.f, 0.f, 0.f};

        prefetch(0, 0);
        for (int kc = 0; kc < 8; kc++) {
            if (kc < 7) {
                prefetch(kc + 1, (kc + 1) & 1);
                asm volatile("cp.async.wait_group 1;\n");
            } else {
                asm volatile("cp.async.wait_group 0;\n");
            }
            __syncthreads();
            const int buf = kc & 1;
            const uint32_t abh = s_hbh + (uint32_t)(buf * (64 * HP) + a_row * HP + a_k) * 2;
            const uint32_t abl = s_hbl + (uint32_t)(buf * (64 * HP) + a_row * HP + a_k) * 2;
#pragma unroll
            for (int ks = 0; ks < 8; ks++) {
                const int k0 = ks * 16;
                uint32_t ah[4], al[4];
                ldsm4(ah, abh + k0 * 2);
                ldsm4(al, abl + k0 * 2);
#pragma unroll
                for (int nt = 0; nt < 3; nt++) {
                    uint32_t bh[2], bl[2];
                    // FIX (R2): weight SMEM spans full K=1024 -> include kc*128 chunk base
                    const uint32_t boff =
                        (uint32_t)((nt * 8 + b_col) * WP + kc * 128 + k0 + b_k) * 2;
                    ldsm2(bh, s_whi + boff);
                    ldsm2(bl, s_wlo + boff);
                    float* acc = (nt == 0) ? accR : (nt == 1) ? accZ : accN;
                    mma_bf16(acc, ah, bh);
                    mma_bf16(acc, al, bh);
                    mma_bf16(acc, ah, bl);
                }
            }
            __syncthreads();
        }

        // --- epilogue: gates + h update for this block's 8 j-columns ---
#pragma unroll
        for (int e = 0; e < 4; e++) {
            const int b = (w << 4) + (lane >> 2) + ((e >> 1) << 3);
            const int col = ((lane & 3) << 1) + (e & 1);
            const int j = jb * 8 + col;
            const int tok = stok[b];
            const float* Pp = g_P + (size_t)tok * (3 * HH) + j;
            const float r = sigf(Pp[0] + accR[e]);
            const float z = sigf(Pp[HH] + accZ[e]);
            const float n = tanhf(Pp[2 * HH] + r * (accN[e] + sbhn[col]));
            const float hold = __bfloat162float(hH[b * HH + j]) + __bfloat162float(hL[b * HH + j]);
            const float hn = n + z * (hold - n);  // (1-z)*n + z*h
            __nv_bfloat16 hi = __float2bfloat16_rn(hn);
            g_h_hi[(size_t)(t + 1) * (BB * HH) + b * HH + j] = hi;
            g_h_lo[(size_t)(t + 1) * (BB * HH) + b * HH + j] =
                __float2bfloat16_rn(hn - __bfloat162float(hi));
        }

        // --- global step barrier (all 128 CTAs co-resident by construction) ---
        __threadfence();
        __syncthreads();
        if (tid == 0) {
            atomicAdd(&g_bar[t], 1u);
            while (((volatile unsigned*)g_bar)[t] < (unsigned)NBLK) { __nanosleep(64); }
            __threadfence();
        }
        __syncthreads();
    }
}

// ============================================================================
// carry output: reconstruct h[512] to fp32
// ============================================================================
__global__ void k_carry_out(float* __restrict__ out) {
    int i = blockIdx.x * blockDim.x + threadIdx.x;
    if (i >= BB * HH) return;
    size_t off = (size_t)SS * (BB * HH) + i;
    out[i] = __bfloat162float(g_h_hi[off]) + __bfloat162float(g_h_lo[off]);
}

// ============================================================================
// logits GEMM: [32768,1024] @ WcT + bc, split-bf16 mma, m64 x n64 per block
// ============================================================================
__global__ void __launch_bounds__(128, 1) k_logits(float* __restrict__ out) {
    extern __shared__ char smem[];
    __nv_bfloat16* Ah = (__nv_bfloat16*)smem;      // 2*64*HP
    __nv_bfloat16* Al = Ah + 2 * 64 * HP;
    __nv_bfloat16* Bh = Al + 2 * 64 * HP;
    __nv_bfloat16* Bl = Bh + 2 * 64 * HP;

    const int tid = threadIdx.x;
    const int w = tid >> 5, lane = tid & 31;
    const int r0 = blockIdx.x * 64;            // global row block (row = b*512 + t)
    const int bidx = r0 >> 9;                  // batch
    const int t0 = r0 & (SS - 1);              // time offset
    const int o0 = blockIdx.y * 64;

    const __nv_bfloat16* srcAh = g_h_hi + (size_t)(t0 + 1) * (BB * HH) + (size_t)bidx * HH;
    const __nv_bfloat16* srcAl = g_h_lo + (size_t)(t0 + 1) * (BB * HH) + (size_t)bidx * HH;
    const __nv_bfloat16* srcBh = g_WcT_hi + (size_t)o0 * HH;
    const __nv_bfloat16* srcBl = g_WcT_lo + (size_t)o0 * HH;

    auto prefetch = [&](int kc, int buf) {
        for (int u = tid; u < 1024; u += 128) {
            int row = u >> 4, q = u & 15;
            cp16(Ah + buf * (64 * HP) + row * HP + q * 8,
                 srcAh + (size_t)row * (BB * HH) + kc * 128 + q * 8);
            cp16(Al + buf * (64 * HP) + row * HP + q * 8,
                 srcAl + (size_t)row * (BB * HH) + kc * 128 + q * 8);
            cp16(Bh + buf * (64 * HP) + row * HP + q * 8,
                 srcBh + (size_t)row * HH + kc * 128 + q * 8);
            cp16(Bl + buf * (64 * HP) + row * HP + q * 8,
                 srcBl + (size_t)row * HH + kc * 128 + q * 8);
        }
        cp_commit();
    };

    const uint32_t sAh = (uint32_t)__cvta_generic_to_shared(Ah);
    const uint32_t sAl = (uint32_t)__cvta_generic_to_shared(Al);
    const uint32_t sBh = (uint32_t)__cvta_generic_to_shared(Bh);
    const uint32_t sBl = (uint32_t)__cvta_generic_to_shared(Bl);

    const int a_rl = lane & 15;
    const int a_k  = (lane >> 4) << 3;
    const int b_cl = lane & 7;
    const int b_k  = ((lane >> 3) & 1) << 3;

    float acc[4][2][4];
#pragma unroll
    for (int mt = 0; mt < 4; mt++)
#pragma unroll
        for (int nt = 0; nt < 2; nt++)
#pragma unroll
            for (int e = 0; e < 4; e++) acc[mt][nt][e] = 0.f;

    prefetch(0, 0);
    for (int kc = 0; kc < 8; kc++) {
        if (kc < 7) {
            prefetch(kc + 1, (kc + 1) & 1);
            asm volatile("cp.async.wait_group 1;\n");
        } else {
            asm volatile("cp.async.wait_group 0;\n");
        }
        __syncthreads();
        const int buf = kc & 1;
#pragma unroll
        for (int ks = 0; ks < 8; ks++) {
            const int k0 = ks * 16;
            uint32_t ah[4][4], al[4][4];
#pragma unroll
            for (int mt = 0; mt < 4; mt++) {
                const uint32_t ao =
                    (uint32_t)(buf * (64 * HP) + (mt * 16 + a_rl) * HP + k0 + a_k) * 2;
                ldsm4(ah[mt], sAh + ao);
                ldsm4(al[mt], sAl + ao);
            }
#pragma unroll
            for (int nt = 0; nt < 2; nt++) {
                const int colg = (w * 2 + nt) * 8 + b_cl;
                const uint32_t bo = (uint32_t)(buf * (64 * HP) + colg * HP + k0 + b_k) * 2;
                uint32_t bh[2], bl[2];
                ldsm2(bh, sBh + bo);
                ldsm2(bl, sBl + bo);
#pragma unroll
                for (int mt = 0; mt < 4; mt++) {
                    mma_bf16(acc[mt][nt], ah[mt], bh);
                    mma_bf16(acc[mt][nt], al[mt], bh);
                    mma_bf16(acc[mt][nt], ah[mt], bl);
                }
            }
        }
        __syncthreads();
    }

#pragma unroll
    for (int mt = 0; mt < 4; mt++)
#pragma unroll
        for (int nt = 0; nt < 2; nt++)
#pragma unroll
            for (int e = 0; e < 4; e++) {
                const int row = r0 + mt * 16 + (lane >> 2) + ((e >> 1) << 3);
                const int o = o0 + (w * 2 + nt) * 8 + ((lane & 3) << 1) + (e & 1);
                out[(size_t)row * OO + o] = acc[mt][nt][e] + g_bc[o];
            }
}

// ============================================================================
// launcher
// ============================================================================
extern "C" void kernel_launch(void* const* d_in, const int* in_sizes, int n_in,
                              void* d_out, int out_size) {
    const int*   inputs = (const int*)d_in[0];
    const float* carry  = (const float*)d_in[1];
    const float* emb    = (const float*)d_in[2];
    const float* Wir    = (const float*)d_in[3];
    const float* bir    = (const float*)d_in[4];
    const float* Whr    = (const float*)d_in[5];
    const float* Wiz    = (const float*)d_in[6];
    const float* biz    = (const float*)d_in[7];
    const float* Whz    = (const float*)d_in[8];
    const float* Win    = (const float*)d_in[9];
    const float* bin_   = (const float*)d_in[10];
    const float* Whn    = (const float*)d_in[11];
    const float* bhn    = (const float*)d_in[12];
    const float* Wh     = (const float*)d_in[13];
    const float* bh     = (const float*)d_in[14];
    const float* Wo     = (const float*)d_in[15];
    const float* bo     = (const float*)d_in[16];

    float* out = (float*)d_out;

    const int GRU_SMEM = (24 * WP * 2 + 2 * 64 * HP * 2) * 2 + 64 * 4 + 8 * 4; // 168992
    const int LOG_SMEM = 4 * (2 * 64 * HP) * 2;                                 // 139264
    cudaFuncSetAttribute(k_gru, cudaFuncAttributeMaxDynamicSharedMemorySize, GRU_SMEM);
    cudaFuncSetAttribute(k_logits, cudaFuncAttributeMaxDynamicSharedMemorySize, LOG_SMEM);

    k_zero_bar<<<2, 256>>>();
    k_pack_carry<<<(BB * HH + 255) / 256, 256>>>(carry);
    k_pack_w<<<(NBLK * 24 * HH + 255) / 256, 256>>>(Whr, Whz, Whn);
    k_build_P<<<(VV * 3 * HH + 255) / 256, 256>>>(emb, Wir, bir, Wiz, biz, Win, bin_);
    k_build_Wc<<<(HH * OO + 255) / 256, 256>>>(Wh, bh, Wo, bo);

    k_gru<<<NBLK, 128, GRU_SMEM>>>(inputs, bhn);

    k_carry_out<<<(BB * HH + 255) / 256, 256>>>(out);

    dim3 lgrid(BB * SS / 64, OO / 64);  // (512, 2)
    k_logits<<<lgrid, 128, LOG_SMEM>>>(out + (size_t)BB * HH);
}

// round 7
// speedup vs baseline: 1.2567x; 1.2567x over previous
#include <cuda_runtime.h>
#include <cuda_bf16.h>
#include <cstdint>
#include <math.h>

// Problem constants
#define BB 64
#define SS 512
#define EE 128
#define HH 1024
#define VV 128
#define OO 128
#define NBLK 128          // GRU CTAs; each owns 8 j-columns (x3 gates = 24 weight rows)
#define HP 136            // padded row (elems) for logits kernel SMEM
#define WP 1032           // padded row (elems) for weight SMEM

// h global layout: per step, 8 chunks; each chunk = [64 rows x 272B hi][64 x 272B lo]
#define ROWB 272                      // 136 elems * 2B (row stride inside a chunk)
#define HALF_CHUNK 17408              // 64*272
#define CHUNK_BYTES 34816             // hi+lo
#define STEP_BYTES 278528             // 8*CHUNK_BYTES

// k_gru SMEM map (bytes)
#define W_HI_OFF 512
#define W_LO_OFF 50048                // 512 + 24*1032*2
#define A_OFF    99584                // 50048 + 49536
#define GRU_SMEM_BYTES 204032         // 99584 + 3*34816

// ---------------- device scratch (no runtime allocation allowed) ------------
__device__ __align__(1024) unsigned char g_h[(size_t)(SS + 1) * STEP_BYTES];
__device__ __nv_bfloat16 g_Wg_hi[(size_t)NBLK * 24 * HH];     // gate weights hi [jb][c][k]
__device__ __nv_bfloat16 g_Wg_lo[(size_t)NBLK * 24 * HH];     // gate weights lo
__device__ float g_P[(size_t)VV * 3 * HH];                    // input preacts per token
__device__ __nv_bfloat16 g_WcT_hi[(size_t)OO * HH];           // (Wh@Wo)^T hi  [o][k]
__device__ __nv_bfloat16 g_WcT_lo[(size_t)OO * HH];           // (Wh@Wo)^T lo
__device__ float g_bc[OO];                                    // bh@Wo + bo
__device__ unsigned g_bar[SS];                                // per-step barrier counters

// byte offset of h(t, b, j) hi part; lo part = +HALF_CHUNK
__host__ __device__ __forceinline__ size_t haddr(int t, int b, int j) {
    return (size_t)t * STEP_BYTES + (size_t)(j >> 7) * CHUNK_BYTES +
           (size_t)b * ROWB + (size_t)(j & 127) * 2;
}

// ---------------- helpers ----------------------------------------------------
__device__ __forceinline__ uint32_t smem_u32(const void* p) {
    uint32_t a;
    asm("{ .reg .u64 t; cvta.to.shared.u64 t, %1; cvt.u32.u64 %0, t; }" : "=r"(a) : "l"(p));
    return a;
}
__device__ __forceinline__ void cp16(void* dst, const void* src) {
    unsigned d = (unsigned)__cvta_generic_to_shared(dst);
    asm volatile("cp.async.cg.shared.global [%0], [%1], 16;\n" ::"r"(d), "l"(src));
}
__device__ __forceinline__ void cp_commit() { asm volatile("cp.async.commit_group;\n"); }

__device__ __forceinline__ void mbar_init(uint32_t mbar, uint32_t cnt) {
    asm volatile("mbarrier.init.shared.b64 [%0], %1;" ::"r"(mbar), "r"(cnt) : "memory");
}
__device__ __forceinline__ void mbar_expect(uint32_t mbar, uint32_t bytes) {
    asm volatile("mbarrier.arrive.expect_tx.shared.b64 _, [%0], %1;"
                 ::"r"(mbar), "r"(bytes) : "memory");
}
__device__ __forceinline__ void mbar_wait(uint32_t mbar, int parity) {
    asm volatile(
        "{\n\t.reg .pred P1;\n\t"
        "W_%=:\n\t"
        "mbarrier.try_wait.parity.acquire.cta.shared::cta.b64 P1, [%0], %1, 0x989680;\n\t"
        "@P1 bra.uni D_%=;\n\t"
        "bra.uni W_%=;\n\t"
        "D_%=:\n\t}"
        ::"r"(mbar), "r"(parity) : "memory");
}
__device__ __forceinline__ void bulk_g2s(uint32_t dst, const void* src, uint32_t bytes,
                                         uint32_t mbar) {
    asm volatile(
        "cp.async.bulk.shared::cluster.global.mbarrier::complete_tx::bytes [%0], [%1], %2, [%3];"
        ::"r"(dst), "l"(src), "r"(bytes), "r"(mbar) : "memory");
}

__device__ __forceinline__ void ldsm4(uint32_t* r, uint32_t saddr) {
    asm volatile("ldmatrix.sync.aligned.m8n8.x4.shared.b16 {%0,%1,%2,%3}, [%4];\n"
                 : "=r"(r[0]), "=r"(r[1]), "=r"(r[2]), "=r"(r[3]) : "r"(saddr));
}
__device__ __forceinline__ void ldsm2(uint32_t* r, uint32_t saddr) {
    asm volatile("ldmatrix.sync.aligned.m8n8.x2.shared.b16 {%0,%1}, [%2];\n"
                 : "=r"(r[0]), "=r"(r[1]) : "r"(saddr));
}
__device__ __forceinline__ void mma_bf16(float* c, const uint32_t* a, const uint32_t* b) {
    asm volatile(
        "mma.sync.aligned.m16n8k16.row.col.f32.bf16.bf16.f32 "
        "{%0,%1,%2,%3},{%4,%5,%6,%7},{%8,%9},{%0,%1,%2,%3};\n"
        : "+f"(c[0]), "+f"(c[1]), "+f"(c[2]), "+f"(c[3])
        : "r"(a[0]), "r"(a[1]), "r"(a[2]), "r"(a[3]), "r"(b[0]), "r"(b[1]));
}
__device__ __forceinline__ float sigf(float x) { return 1.0f / (1.0f + expf(-x)); }

// ============================================================================
// init kernels
// ============================================================================
__global__ void k_zero_bar() {
    int i = blockIdx.x * blockDim.x + threadIdx.x;
    if (i < SS) g_bar[i] = 0u;
}

__global__ void k_pack_carry(const float* __restrict__ carry) {
    int i = blockIdx.x * blockDim.x + threadIdx.x;
    if (i >= BB * HH) return;
    int b = i >> 10, j = i & (HH - 1);
    float v = carry[i];
    __nv_bfloat16 hi = __float2bfloat16_rn(v);
    size_t ha = haddr(0, b, j);
    *(__nv_bfloat16*)(g_h + ha) = hi;
    *(__nv_bfloat16*)(g_h + ha + HALF_CHUNK) = __float2bfloat16_rn(v - __bfloat162float(hi));
}

__global__ void k_pack_w(const float* __restrict__ Whr, const float* __restrict__ Whz,
                         const float* __restrict__ Whn) {
    int idx = blockIdx.x * blockDim.x + threadIdx.x;
    if (idx >= NBLK * 24 * HH) return;
    int jb = idx / (24 * HH);
    int rem = idx - jb * (24 * HH);
    int c = rem >> 10;         // 0..23
    int k = rem & (HH - 1);
    int g = c >> 3;
    int j = (jb << 3) + (c & 7);
    const float* Wg = (g == 0) ? Whr : (g == 1) ? Whz : Whn;
    float v = Wg[(size_t)k * HH + j];
    __nv_bfloat16 hi = __float2bfloat16_rn(v);
    g_Wg_hi[idx] = hi;
    g_Wg_lo[idx] = __float2bfloat16_rn(v - __bfloat162float(hi));
}

__global__ void k_build_P(const float* __restrict__ emb,
                          const float* __restrict__ Wir, const float* __restrict__ bir,
                          const float* __restrict__ Wiz, const float* __restrict__ biz,
                          const float* __restrict__ Win, const float* __restrict__ bin_) {
    int idx = blockIdx.x * blockDim.x + threadIdx.x;
    if (idx >= VV * 3 * HH) return;
    int j = idx & (HH - 1);
    int g = (idx >> 10) % 3;
    int v = idx / (3 * HH);
    const float* W = (g == 0) ? Wir : (g == 1) ? Wiz : Win;
    const float* bb = (g == 0) ? bir : (g == 1) ? biz : bin_;
    float a = bb[j];
#pragma unroll 8
    for (int k = 0; k < EE; k++) a += emb[v * EE + k] * W[(size_t)k * HH + j];
    g_P[idx] = a;
}

__global__ void k_build_Wc(const float* __restrict__ Wh, const float* __restrict__ bh,
                           const float* __restrict__ Wo, const float* __restrict__ bo) {
    int idx = blockIdx.x * blockDim.x + threadIdx.x;
    if (idx >= HH * OO) return;
    int o = idx & (OO - 1);
    int k = idx >> 7;
    float a = 0.f;
#pragma unroll 8
    for (int j = 0; j < HH; j++) a += Wh[(size_t)k * HH + j] * Wo[(size_t)j * OO + o];
    __nv_bfloat16 hi = __float2bfloat16_rn(a);
    g_WcT_hi[(size_t)o * HH + k] = hi;
    g_WcT_lo[(size_t)o * HH + k] = __float2bfloat16_rn(a - __bfloat162float(hi));
    if (k == 0) {
        float c = bo[o];
#pragma unroll 8
        for (int j = 0; j < HH; j++) c += bh[j] * Wo[(size_t)j * OO + o];
        g_bc[o] = c;
    }
}

// ============================================================================
// persistent GRU kernel: 128 CTAs x 128 threads, weights SMEM-resident,
// h streamed per chunk via single cp.async.bulk into a 3-stage mbarrier ring.
// ============================================================================
__global__ void __launch_bounds__(128, 1)
k_gru(const int* __restrict__ inputs, const float* __restrict__ bhn) {
    extern __shared__ char smem[];
    const int tid = threadIdx.x;
    const int jb = blockIdx.x;
    const int w = tid >> 5, lane = tid & 31;
    const uint32_t sb = smem_u32(smem);
    const uint32_t mb0 = sb, mb1 = sb + 8, mb2 = sb + 16;
    int* stok = (int*)(smem + 32);
    float* sbhn = (float*)(smem + 288);
    __nv_bfloat16* whi = (__nv_bfloat16*)(smem + W_HI_OFF);
    __nv_bfloat16* wlo = (__nv_bfloat16*)(smem + W_LO_OFF);

    if (tid == 0) { mbar_init(mb0, 1); mbar_init(mb1, 1); mbar_init(mb2, 1); }

    // one-time weight slice load (96KB)
    {
        const __nv_bfloat16* srcH = g_Wg_hi + (size_t)jb * 24 * HH;
        const __nv_bfloat16* srcL = g_Wg_lo + (size_t)jb * 24 * HH;
        for (int u = tid; u < 3072; u += 128) {
            int c = u >> 7, q = u & 127;
            cp16(whi + c * WP + q * 8, srcH + c * HH + q * 8);
            cp16(wlo + c * WP + q * 8, srcL + c * HH + q * 8);
        }
    }
    if (tid < 8) sbhn[tid] = bhn[jb * 8 + tid];
    cp_commit();
    asm volatile("cp.async.wait_group 0;\n" ::: "memory");
    __syncthreads();

    const uint32_t s_whi = sb + W_HI_OFF, s_wlo = sb + W_LO_OFF, sA = sb + A_OFF;
    const int a_row = (w << 4) + (lane & 15);
    const int a_k   = (lane >> 4) << 3;
    const int b_col = lane & 7;
    const int b_k   = ((lane >> 3) & 1) << 3;

    int ph0 = 0, ph1 = 0, ph2 = 0;

    for (int t = 0; t < SS; t++) {
        if (tid < 64) stok[tid] = inputs[tid * SS + t];
        const unsigned char* hbase = g_h + (size_t)t * STEP_BYTES;

        if (tid == 0) {
            mbar_expect(mb0, CHUNK_BYTES);
            bulk_g2s(sA, hbase, CHUNK_BYTES, mb0);
            mbar_expect(mb1, CHUNK_BYTES);
            bulk_g2s(sA + CHUNK_BYTES, hbase + CHUNK_BYTES, CHUNK_BYTES, mb1);
            mbar_expect(mb2, CHUNK_BYTES);
            bulk_g2s(sA + 2 * CHUNK_BYTES, hbase + 2 * (size_t)CHUNK_BYTES, CHUNK_BYTES, mb2);
        }

        float accR[4] = {0.f, 0.f, 0.f, 0.f};
        float accZ[4] = {0.f, 0.f, 0.f, 0.f};
        float accN[4] = {0.f, 0.f, 0.f, 0.f};

#pragma unroll
        for (int kc = 0; kc < 8; kc++) {
            const int buf = kc % 3;
            const uint32_t mb = (buf == 0) ? mb0 : (buf == 1) ? mb1 : mb2;
            int* php = (buf == 0) ? &ph0 : (buf == 1) ? &ph1 : &ph2;
            mbar_wait(mb, *php);
            *php ^= 1;

            const uint32_t abh = sA + buf * CHUNK_BYTES + a_row * ROWB + a_k * 2;
#pragma unroll
            for (int ks = 0; ks < 8; ks++) {
                const int k0 = ks * 16;
                uint32_t ah[4], al[4];
                ldsm4(ah, abh + k0 * 2);
                ldsm4(al, abh + HALF_CHUNK + k0 * 2);
#pragma unroll
                for (int nt = 0; nt < 3; nt++) {
                    uint32_t bh2[2], bl2[2];
                    const uint32_t boff =
                        (uint32_t)((nt * 8 + b_col) * WP + kc * 128 + k0 + b_k) * 2;
                    ldsm2(bh2, s_whi + boff);
                    ldsm2(bl2, s_wlo + boff);
                    float* acc = (nt == 0) ? accR : (nt == 1) ? accZ : accN;
                    mma_bf16(acc, ah, bh2);
                    mma_bf16(acc, al, bh2);
                    mma_bf16(acc, ah, bl2);
                }
            }
            __syncthreads();  // all warps done reading buf
            if (kc < 5 && tid == 0) {
                mbar_expect(mb, CHUNK_BYTES);
                bulk_g2s(sA + buf * CHUNK_BYTES, hbase + (size_t)(kc + 3) * CHUNK_BYTES,
                         CHUNK_BYTES, mb);
            }
        }

        // --- epilogue: gates + h update for this block's 8 j-columns ---
#pragma unroll
        for (int e = 0; e < 4; e++) {
            const int b = (w << 4) + (lane >> 2) + ((e >> 1) << 3);
            const int col = ((lane & 3) << 1) + (e & 1);
            const int j = jb * 8 + col;
            const int tok = stok[b];
            const float* Pp = g_P + (size_t)tok * (3 * HH) + j;
            const float r = sigf(Pp[0] + accR[e]);
            const float z = sigf(Pp[HH] + accZ[e]);
            const float nv = tanhf(Pp[2 * HH] + r * (accN[e] + sbhn[col]));
            const size_t hao = haddr(t, b, j);
            const float hold = __bfloat162float(*(const __nv_bfloat16*)(g_h + hao)) +
                               __bfloat162float(*(const __nv_bfloat16*)(g_h + hao + HALF_CHUNK));
            const float hn = nv + z * (hold - nv);  // (1-z)*n + z*h
            const __nv_bfloat16 hi = __float2bfloat16_rn(hn);
            const size_t han = haddr(t + 1, b, j);
            *(__nv_bfloat16*)(g_h + han) = hi;
            *(__nv_bfloat16*)(g_h + han + HALF_CHUNK) =
                __float2bfloat16_rn(hn - __bfloat162float(hi));
        }

        // --- global step barrier (128 co-resident CTAs by construction) ---
        __threadfence();
        __syncthreads();
        if (tid == 0) {
            atomicAdd(&g_bar[t], 1u);
            while (((volatile unsigned*)g_bar)[t] < (unsigned)NBLK) { __nanosleep(64); }
            __threadfence();
        }
        __syncthreads();
    }
}

// ============================================================================
// carry output: reconstruct h[512] to fp32
// ============================================================================
__global__ void k_carry_out(float* __restrict__ out) {
    int i = blockIdx.x * blockDim.x + threadIdx.x;
    if (i >= BB * HH) return;
    int b = i >> 10, j = i & (HH - 1);
    size_t ha = haddr(SS, b, j);
    out[i] = __bfloat162float(*(const __nv_bfloat16*)(g_h + ha)) +
             __bfloat162float(*(const __nv_bfloat16*)(g_h + ha + HALF_CHUNK));
}

// ============================================================================
// logits GEMM: [32768,1024] @ WcT + bc, split-bf16 mma, m64 x n64 per block
// ============================================================================
__global__ void __launch_bounds__(128, 1) k_logits(float* __restrict__ out) {
    extern __shared__ char smem[];
    __nv_bfloat16* Ah = (__nv_bfloat16*)smem;      // 2*64*HP
    __nv_bfloat16* Al = Ah + 2 * 64 * HP;
    __nv_bfloat16* Bh = Al + 2 * 64 * HP;
    __nv_bfloat16* Bl = Bh + 2 * 64 * HP;

    const int tid = threadIdx.x;
    const int w = tid >> 5, lane = tid & 31;
    const int r0 = blockIdx.x * 64;            // global row block (row = b*512 + t)
    const int bidx = r0 >> 9;                  // batch
    const int t0 = r0 & (SS - 1);              // time offset
    const int o0 = blockIdx.y * 64;

    const __nv_bfloat16* srcBh = g_WcT_hi + (size_t)o0 * HH;
    const __nv_bfloat16* srcBl = g_WcT_lo + (size_t)o0 * HH;

    auto prefetch = [&](int kc, int buf) {
        for (int u = tid; u < 1024; u += 128) {
            int row = u >> 4, q = u & 15;
            const unsigned char* srcA = g_h + (size_t)(t0 + row + 1) * STEP_BYTES +
                                        (size_t)kc * CHUNK_BYTES + (size_t)bidx * ROWB +
                                        (size_t)q * 16;
            cp16(Ah + buf * (64 * HP) + row * HP + q * 8, srcA);
            cp16(Al + buf * (64 * HP) + row * HP + q * 8, srcA + HALF_CHUNK);
            cp16(Bh + buf * (64 * HP) + row * HP + q * 8,
                 srcBh + (size_t)row * HH + kc * 128 + q * 8);
            cp16(Bl + buf * (64 * HP) + row * HP + q * 8,
                 srcBl + (size_t)row * HH + kc * 128 + q * 8);
        }
        cp_commit();
    };

    const uint32_t sAh = (uint32_t)__cvta_generic_to_shared(Ah);
    const uint32_t sAl = (uint32_t)__cvta_generic_to_shared(Al);
    const uint32_t sBh = (uint32_t)__cvta_generic_to_shared(Bh);
    const uint32_t sBl = (uint32_t)__cvta_generic_to_shared(Bl);

    const int a_rl = lane & 15;
    const int a_k  = (lane >> 4) << 3;
    const int b_cl = lane & 7;
    const int b_k  = ((lane >> 3) & 1) << 3;

    float acc[4][2][4];
#pragma unroll
    for (int mt = 0; mt < 4; mt++)
#pragma unroll
        for (int nt = 0; nt < 2; nt++)
#pragma unroll
            for (int e = 0; e < 4; e++) acc[mt][nt][e] = 0.f;

    prefetch(0, 0);
    for (int kc = 0; kc < 8; kc++) {
        if (kc < 7) {
            prefetch(kc + 1, (kc + 1) & 1);
            asm volatile("cp.async.wait_group 1;\n");
        } else {
            asm volatile("cp.async.wait_group 0;\n");
        }
        __syncthreads();
        const int buf = kc & 1;
#pragma unroll
        for (int ks = 0; ks < 8; ks++) {
            const int k0 = ks * 16;
            uint32_t ah[4][4], al[4][4];
#pragma unroll
            for (int mt = 0; mt < 4; mt++) {
                const uint32_t ao =
                    (uint32_t)(buf * (64 * HP) + (mt * 16 + a_rl) * HP + k0 + a_k) * 2;
                ldsm4(ah[mt], sAh + ao);
                ldsm4(al[mt], sAl + ao);
            }
#pragma unroll
            for (int nt = 0; nt < 2; nt++) {
                const int colg = (w * 2 + nt) * 8 + b_cl;
                const uint32_t bo = (uint32_t)(buf * (64 * HP) + colg * HP + k0 + b_k) * 2;
                uint32_t bh2[2], bl2[2];
                ldsm2(bh2, sBh + bo);
                ldsm2(bl2, sBl + bo);
#pragma unroll
                for (int mt = 0; mt < 4; mt++) {
                    mma_bf16(acc[mt][nt], ah[mt], bh2);
                    mma_bf16(acc[mt][nt], al[mt], bh2);
                    mma_bf16(acc[mt][nt], ah[mt], bl2);
                }
            }
        }
        __syncthreads();
    }

#pragma unroll
    for (int mt = 0; mt < 4; mt++)
#pragma unroll
        for (int nt = 0; nt < 2; nt++)
#pragma unroll
            for (int e = 0; e < 4; e++) {
                const int row = r0 + mt * 16 + (lane >> 2) + ((e >> 1) << 3);
                const int o = o0 + (w * 2 + nt) * 8 + ((lane & 3) << 1) + (e & 1);
                out[(size_t)row * OO + o] = acc[mt][nt][e] + g_bc[o];
            }
}

// ============================================================================
// launcher
// ============================================================================
extern "C" void kernel_launch(void* const* d_in, const int* in_sizes, int n_in,
                              void* d_out, int out_size) {
    const int*   inputs = (const int*)d_in[0];
    const float* carry  = (const float*)d_in[1];
    const float* emb    = (const float*)d_in[2];
    const float* Wir    = (const float*)d_in[3];
    const float* bir    = (const float*)d_in[4];
    const float* Whr    = (const float*)d_in[5];
    const float* Wiz    = (const float*)d_in[6];
    const float* biz    = (const float*)d_in[7];
    const float* Whz    = (const float*)d_in[8];
    const float* Win    = (const float*)d_in[9];
    const float* bin_   = (const float*)d_in[10];
    const float* Whn    = (const float*)d_in[11];
    const float* bhn    = (const float*)d_in[12];
    const float* Wh     = (const float*)d_in[13];
    const float* bh     = (const float*)d_in[14];
    const float* Wo     = (const float*)d_in[15];
    const float* bo     = (const float*)d_in[16];

    float* out = (float*)d_out;

    const int LOG_SMEM = 4 * (2 * 64 * HP) * 2;  // 139264
    cudaFuncSetAttribute(k_gru, cudaFuncAttributeMaxDynamicSharedMemorySize, GRU_SMEM_BYTES);
    cudaFuncSetAttribute(k_logits, cudaFuncAttributeMaxDynamicSharedMemorySize, LOG_SMEM);

    k_zero_bar<<<2, 256>>>();
    k_pack_carry<<<(BB * HH + 255) / 256, 256>>>(carry);
    k_pack_w<<<(NBLK * 24 * HH + 255) / 256, 256>>>(Whr, Whz, Whn);
    k_build_P<<<(VV * 3 * HH + 255) / 256, 256>>>(emb, Wir, bir, Wiz, biz, Win, bin_);
    k_build_Wc<<<(HH * OO + 255) / 256, 256>>>(Wh, bh, Wo, bo);

    k_gru<<<NBLK, 128, GRU_SMEM_BYTES>>>(inputs, bhn);

    k_carry_out<<<(BB * HH + 255) / 256, 256>>>(out);

    dim3 lgrid(BB * SS / 64, OO / 64);  // (512, 2)
    k_logits<<<lgrid, 128, LOG_SMEM>>>(out + (size_t)BB * HH);
}